// round 3
// baseline (speedup 1.0000x reference)
#include <cuda_runtime.h>

#define NN 50000
#define DD 128
#define EE 800000

// ---- scratch (__device__ globals: allocation-free) ----
__device__ int   g_cntrow[NN];     // degree over row (for CSR)
__device__ int   g_degcol[NN];     // degree over col (for norm)
__device__ int   g_off[NN + 1];    // CSR row offsets
__device__ int   g_cursor[NN];     // scatter cursors
__device__ int   g_scol[EE];       // edges sorted by row: col ids
__device__ float g_dis[NN];        // deg_col^-0.5 (0 if deg==0)
__device__ unsigned int g_maxbits; // ordered-float max of x; zero-init acts as -inf,
                                   // atomicMax is idempotent across graph replays
__device__ float2 g_ppM;           // (pp, M = pp*max(x))

__device__ __forceinline__ unsigned int ford(float f) {
    unsigned int b = __float_as_uint(f);
    return (b & 0x80000000u) ? ~b : (b | 0x80000000u);
}
__device__ __forceinline__ float funord(unsigned int u) {
    unsigned int b = (u & 0x80000000u) ? (u & 0x7FFFFFFFu) : ~u;
    return __uint_as_float(b);
}

// L1: zero the per-call counters AND reduce global max of x (independent arrays)
__global__ void k_zero_max(const float* __restrict__ x) {
    const int gsz = gridDim.x * blockDim.x;
    int gi = blockIdx.x * blockDim.x + threadIdx.x;
    for (int i = gi; i < NN; i += gsz) { g_cntrow[i] = 0; g_degcol[i] = 0; }

    float m = -3.402823466e38f;
    const float4* x4 = (const float4*)x;
    const int n4 = (NN * DD) / 4;
    for (int i = gi; i < n4; i += gsz) {
        float4 v = x4[i];
        m = fmaxf(m, fmaxf(fmaxf(v.x, v.y), fmaxf(v.z, v.w)));
    }
#pragma unroll
    for (int o = 16; o; o >>= 1) m = fmaxf(m, __shfl_xor_sync(~0u, m, o));
    __shared__ float sm[32];
    int lane = threadIdx.x & 31, w = threadIdx.x >> 5;
    if (lane == 0) sm[w] = m;
    __syncthreads();
    if (w == 0) {
        m = (lane < (int)(blockDim.x >> 5)) ? sm[lane] : -3.402823466e38f;
#pragma unroll
        for (int o = 16; o; o >>= 1) m = fmaxf(m, __shfl_xor_sync(~0u, m, o));
        if (lane == 0) atomicMax(&g_maxbits, ford(m));
    }
}

// L2: histogram degrees
__global__ void k_count(const int* __restrict__ ei) {
    int e = blockIdx.x * blockDim.x + threadIdx.x;
    if (e < EE) {
        atomicAdd(&g_cntrow[ei[e]], 1);
        atomicAdd(&g_degcol[ei[EE + e]], 1);
    }
}

// L3: single-block scan of cntrow -> off/cursor, plus dis[] and ppM
__global__ void k_scan_dis(const float* __restrict__ p) {
    const int C = (NN + 1023) / 1024;  // 49 per thread
    __shared__ int part[1024];
    int tid = threadIdx.x;
    int base = tid * C;
    int s = 0;
    for (int k = 0; k < C; k++) {
        int i = base + k;
        s += (i < NN) ? g_cntrow[i] : 0;
    }
    part[tid] = s;
    __syncthreads();
    for (int off = 1; off < 1024; off <<= 1) {
        int t = (tid >= off) ? part[tid - off] : 0;
        __syncthreads();
        part[tid] += t;
        __syncthreads();
    }
    int run = part[tid] - s;  // exclusive prefix of chunk
    for (int k = 0; k < C; k++) {
        int i = base + k;
        if (i < NN) {
            g_off[i] = run;
            g_cursor[i] = run;
            run += g_cntrow[i];
            int dg = g_degcol[i];
            g_dis[i] = (dg > 0) ? rsqrtf((float)dg) : 0.0f;
        }
    }
    if (tid == 1023) g_off[NN] = run;
    if (tid == 0) {
        float pp = 2.0f / (1.0f + __expf(-p[0]));
        g_ppM = make_float2(pp, pp * funord(g_maxbits));
    }
}

// L4: scatter cols into row-sorted order
__global__ void k_scatter(const int* __restrict__ ei) {
    int e = blockIdx.x * blockDim.x + threadIdx.x;
    if (e < EE) {
        int pos = atomicAdd(&g_cursor[ei[e]], 1);
        g_scol[pos] = ei[EE + e];
    }
}

// L5: warp-per-node; lane owns 4 features via float4
__global__ void __launch_bounds__(256) k_main(const float* __restrict__ x,
                                              const float* __restrict__ eps,
                                              float* __restrict__ out) {
    const int warp = blockIdx.x * 8 + (threadIdx.x >> 5);
    if (warp >= NN) return;
    const int lane = threadIdx.x & 31;
    const int r = warp;
    const int start = g_off[r];
    const int end   = g_off[r + 1];
    const float2 ppM = g_ppM;
    const float pp = ppM.x, M = ppM.y;
    const float4* __restrict__ x4 = (const float4*)x;

    float4 num = make_float4(0.f, 0.f, 0.f, 0.f);
    float4 den = make_float4(0.f, 0.f, 0.f, 0.f);

    for (int base = start; base < end; base += 32) {
        int j = base + lane;
        int   c = 0;
        float w = 0.f;
        if (j < end) {
            c = g_scol[j];
            w = __ldg(&g_dis[c]);
        }
        int m = end - base;
        if (m > 32) m = 32;
        int k = 0;
        for (; k + 4 <= m; k += 4) {
            int   c0 = __shfl_sync(~0u, c, k),     c1 = __shfl_sync(~0u, c, k + 1);
            int   c2 = __shfl_sync(~0u, c, k + 2), c3 = __shfl_sync(~0u, c, k + 3);
            float w0 = __shfl_sync(~0u, w, k),     w1 = __shfl_sync(~0u, w, k + 1);
            float w2 = __shfl_sync(~0u, w, k + 2), w3 = __shfl_sync(~0u, w, k + 3);
            float4 t0 = __ldg(&x4[c0 * 32 + lane]);
            float4 t1 = __ldg(&x4[c1 * 32 + lane]);
            float4 t2 = __ldg(&x4[c2 * 32 + lane]);
            float4 t3 = __ldg(&x4[c3 * 32 + lane]);
#define EDGE(t, wk)                                              \
            {                                                    \
                float sx = __expf(fmaf(pp, t.x, -M));            \
                float sy = __expf(fmaf(pp, t.y, -M));            \
                float sz = __expf(fmaf(pp, t.z, -M));            \
                float sw = __expf(fmaf(pp, t.w, -M));            \
                den.x = fmaf(sx, wk, den.x); num.x = fmaf(sx * t.x, wk, num.x); \
                den.y = fmaf(sy, wk, den.y); num.y = fmaf(sy * t.y, wk, num.y); \
                den.z = fmaf(sz, wk, den.z); num.z = fmaf(sz * t.z, wk, num.z); \
                den.w = fmaf(sw, wk, den.w); num.w = fmaf(sw * t.w, wk, num.w); \
            }
            EDGE(t0, w0) EDGE(t1, w1) EDGE(t2, w2) EDGE(t3, w3)
        }
        for (; k < m; k++) {
            int   ck = __shfl_sync(~0u, c, k);
            float wk = __shfl_sync(~0u, w, k);
            float4 t = __ldg(&x4[ck * 32 + lane]);
            EDGE(t, wk)
        }
#undef EDGE
    }

    float dr = g_dis[r];
    float e1 = 1.0f + eps[0];
    float4 xv = __ldg(&x4[r * 32 + lane]);
    float4 o;
    o.x = __fdividef(dr * num.x, fmaf(dr, den.x, 1e-6f)) + e1 * xv.x;
    o.y = __fdividef(dr * num.y, fmaf(dr, den.y, 1e-6f)) + e1 * xv.y;
    o.z = __fdividef(dr * num.z, fmaf(dr, den.z, 1e-6f)) + e1 * xv.z;
    o.w = __fdividef(dr * num.w, fmaf(dr, den.w, 1e-6f)) + e1 * xv.w;
    ((float4*)out)[r * 32 + lane] = o;
}

extern "C" void kernel_launch(void* const* d_in, const int* in_sizes, int n_in,
                              void* d_out, int out_size) {
    const float* x   = (const float*)d_in[0];
    const int*   ei  = (const int*)d_in[1];
    const float* eps = (const float*)d_in[2];
    const float* p   = (const float*)d_in[3];
    float* out = (float*)d_out;

    k_zero_max<<<512, 256>>>(x);
    k_count   <<<(EE + 255) / 256, 256>>>(ei);
    k_scan_dis<<<1, 1024>>>(p);
    k_scatter <<<(EE + 255) / 256, 256>>>(ei);
    k_main    <<<(NN + 7) / 8, 256>>>(x, eps, out);
}